// round 2
// baseline (speedup 1.0000x reference)
#include <cuda_runtime.h>
#include <math_constants.h>

#define NB 32
#define NPROP 256
#define NCLS 19
#define NPTS 4096
#define NBQ 64
#define NCK 64
#define CDIM 256
#define QHD 768
#define VQn 8
#define MROWS (NB*NBQ)                 // 2048 rows per branch
#define OUTROWS 1024                   // (NBQ+NCK)*VQ per batch
#define FEAT_ELEMS (NB*OUTROWS*QHD)    // 25165824

// ---------------- scratch (device globals; no allocation allowed) ----------------
__device__ float g_mn[NB*NPROP*3];
__device__ float g_mx[NB*NPROP*3];
__device__ float g_vol[NB*NPROP];
__device__ float g_pmask[NB*NPROP];
__device__ int   g_match[MROWS];
__device__ int   g_nn[MROWS];
__device__ float g_box_feat[MROWS*CDIM];        // [2048, 256]
__device__ float g_click_in[MROWS*2*CDIM];      // [2048, 512]
__device__ float g_h[2*MROWS*QHD];              // box hidden then click hidden

// ---------------- proposal prep: argmax mask + AABB + volume ----------------
__global__ void prop_prep(const float* __restrict__ logits, const float* __restrict__ corners) {
    int p = blockIdx.x * blockDim.x + threadIdx.x;
    if (p >= NB*NPROP) return;
    const float* l = logits + (size_t)p * NCLS;
    float best = l[0]; int bi = 0;
    #pragma unroll
    for (int k = 1; k < NCLS; k++) { float v = l[k]; if (v > best) { best = v; bi = k; } }
    g_pmask[p] = (bi != NCLS - 1) ? 1.f : 0.f;
    const float* cr = corners + (size_t)p * 24;
    float mn0 = cr[0], mn1 = cr[1], mn2 = cr[2];
    float mx0 = cr[0], mx1 = cr[1], mx2 = cr[2];
    #pragma unroll
    for (int c = 1; c < 8; c++) {
        float x = cr[c*3+0], y = cr[c*3+1], z = cr[c*3+2];
        mn0 = fminf(mn0, x); mx0 = fmaxf(mx0, x);
        mn1 = fminf(mn1, y); mx1 = fmaxf(mx1, y);
        mn2 = fminf(mn2, z); mx2 = fmaxf(mx2, z);
    }
    g_mn[p*3+0] = mn0; g_mn[p*3+1] = mn1; g_mn[p*3+2] = mn2;
    g_mx[p*3+0] = mx0; g_mx[p*3+1] = mx1; g_mx[p*3+2] = mx2;
    g_vol[p] = (mx0-mn0)*(mx1-mn1)*(mx2-mn2);
}

// ---------------- box IoU argmax match ----------------
__global__ void box_match(const float* __restrict__ box_query) {
    __shared__ float s_mn[NPROP*3], s_mx[NPROP*3], s_vol[NPROP], s_msk[NPROP];
    int b = blockIdx.x, t = threadIdx.x;
    if (t < NPROP) {
        int p = b*NPROP + t;
        s_mn[t*3+0] = g_mn[p*3+0]; s_mn[t*3+1] = g_mn[p*3+1]; s_mn[t*3+2] = g_mn[p*3+2];
        s_mx[t*3+0] = g_mx[p*3+0]; s_mx[t*3+1] = g_mx[p*3+1]; s_mx[t*3+2] = g_mx[p*3+2];
        s_vol[t] = g_vol[p]; s_msk[t] = g_pmask[p];
    }
    __syncthreads();
    if (t < NBQ) {
        const float* cq = box_query + ((size_t)b*NBQ + t) * 24;
        float mn0 = cq[0], mn1 = cq[1], mn2 = cq[2];
        float mx0 = cq[0], mx1 = cq[1], mx2 = cq[2];
        #pragma unroll
        for (int c = 1; c < 8; c++) {
            float x = cq[c*3+0], y = cq[c*3+1], z = cq[c*3+2];
            mn0 = fminf(mn0, x); mx0 = fmaxf(mx0, x);
            mn1 = fminf(mn1, y); mx1 = fmaxf(mx1, y);
            mn2 = fminf(mn2, z); mx2 = fmaxf(mx2, z);
        }
        float volq = (mx0-mn0)*(mx1-mn1)*(mx2-mn2);
        float best = -1.f; int bi = 0;
        for (int p = 0; p < NPROP; p++) {
            float ix = fminf(mx0, s_mx[p*3+0]) - fmaxf(mn0, s_mn[p*3+0]);
            float iy = fminf(mx1, s_mx[p*3+1]) - fmaxf(mn1, s_mn[p*3+1]);
            float iz = fminf(mx2, s_mx[p*3+2]) - fmaxf(mn2, s_mn[p*3+2]);
            ix = fmaxf(ix, 0.f); iy = fmaxf(iy, 0.f); iz = fmaxf(iz, 0.f);
            float inter = ix*iy*iz;
            float iou = inter / (volq + s_vol[p] - inter + 1e-8f) * s_msk[p];
            if (iou > best) { best = iou; bi = p; }
        }
        g_match[b*NBQ + t] = bi;
    }
}

// ---------------- gather matched proposal features ----------------
__global__ void gather_box(const float* __restrict__ prop_features) {
    int r = blockIdx.x;                 // 0..2047
    int b = r >> 6;
    int m = g_match[r];
    const float4* src = (const float4*)(prop_features + ((size_t)b*NPROP + m) * CDIM);
    float4* dst = (float4*)(g_box_feat + (size_t)r * CDIM);
    dst[threadIdx.x] = src[threadIdx.x];  // 64 threads x float4 = 256 floats
}

// ---------------- click nearest-neighbor (warp argmin, enc_xyz staged in smem) ----------------
__global__ void click_nn(const float* __restrict__ enc_xyz, const float* __restrict__ click_query) {
    __shared__ float s_xyz[NPTS*3];     // 48 KB
    int b = blockIdx.x, t = threadIdx.x;
    const float* src = enc_xyz + (size_t)b * NPTS * 3;
    for (int i = t; i < NPTS*3; i += 256) s_xyz[i] = src[i];
    __syncthreads();
    int warp = t >> 5, lane = t & 31;
    for (int q = warp; q < NCK; q += 8) {
        const float* cq = click_query + ((size_t)b*NCK + q) * 3;
        float cx = cq[0], cy = cq[1], cz = cq[2];
        float best = CUDART_INF_F; int bi = 0;
        for (int p = lane; p < NPTS; p += 32) {
            float dx = cx - s_xyz[p*3+0];
            float dy = cy - s_xyz[p*3+1];
            float dz = cz - s_xyz[p*3+2];
            float d = dx*dx + dy*dy + dz*dz;
            if (d < best) { best = d; bi = p; }
        }
        #pragma unroll
        for (int off = 16; off; off >>= 1) {
            float ob = __shfl_xor_sync(0xffffffffu, best, off);
            int   oi = __shfl_xor_sync(0xffffffffu, bi, off);
            if (ob < best || (ob == best && oi < bi)) { best = ob; bi = oi; }
        }
        if (lane == 0) g_nn[b*NCK + q] = bi;
    }
}

// ---------------- click input build: gathered features + fourier pos ----------------
__global__ void click_build(const float* __restrict__ enc_features,
                            const float* __restrict__ click_query,
                            const float* __restrict__ pc_min,
                            const float* __restrict__ pc_max,
                            const float* __restrict__ gauss) {
    int r = blockIdx.x, t = threadIdx.x;  // 128 threads
    int b = r >> 6;
    int nn = g_nn[r];
    const float2* src = (const float2*)(enc_features + ((size_t)b*NPTS + nn) * CDIM);
    float2* dst = (float2*)(g_click_in + (size_t)r * 2 * CDIM);
    dst[t] = src[t];                      // 128 x float2 = 256 floats
    const float* cq = click_query + (size_t)r * 3;
    float pr = 0.f;
    #pragma unroll
    for (int d = 0; d < 3; d++) {
        float x01 = (cq[d] - pc_min[b*3+d]) / (pc_max[b*3+d] - pc_min[b*3+d]);
        pr += x01 * 6.283185307179586f * gauss[d*(CDIM/2) + t];
    }
    g_click_in[(size_t)r*2*CDIM + CDIM + t]       = sinf(pr);
    g_click_in[(size_t)r*2*CDIM + CDIM + 128 + t] = cosf(pr);
}

// ---------------- SGEMM 128x128x8, 256 threads, 8x8 per thread ----------------
// mode 0: A=g_box_feat  (K=256), relu -> g_h[0..]
// mode 1: A=g_click_in  (K=512), relu -> g_h[MROWS*QHD..]
// mode 2: A=g_h box half (K=768), out -> d_out remapped, branch_off=0
// mode 3: A=g_h click half (K=768), out -> d_out remapped, branch_off=512
__global__ __launch_bounds__(256, 2) void sgemm128(
        const float* __restrict__ W, const float* __restrict__ bias,
        float* __restrict__ out, int K, int N, int mode) {
    const float* A =
        (mode == 0) ? g_box_feat :
        (mode == 1) ? g_click_in :
        (mode == 2) ? g_h : (g_h + (size_t)MROWS*QHD);

    __shared__ __align__(16) float As[8][128];
    __shared__ __align__(16) float Bs[8][128];

    int tid = threadIdx.x;
    int bm = blockIdx.y, bn = blockIdx.x;
    const float* Ab = A + (size_t)bm * 128 * K;
    const float* Wb = W + (size_t)bn * 128;

    int arow = tid >> 1, acol = (tid & 1) * 4;
    int brow = tid >> 5, bcol = (tid & 31) * 4;
    int ty = tid >> 4, tx = tid & 15;

    float acc[8][8];
    #pragma unroll
    for (int i = 0; i < 8; i++)
        #pragma unroll
        for (int j = 0; j < 8; j++) acc[i][j] = 0.f;

    for (int k0 = 0; k0 < K; k0 += 8) {
        float4 av = *(const float4*)(Ab + (size_t)arow * K + k0 + acol);
        As[acol+0][arow] = av.x; As[acol+1][arow] = av.y;
        As[acol+2][arow] = av.z; As[acol+3][arow] = av.w;
        float4 bv = *(const float4*)(Wb + (size_t)(k0 + brow) * N + bcol);
        *(float4*)(&Bs[brow][bcol]) = bv;
        __syncthreads();
        #pragma unroll
        for (int kk = 0; kk < 8; kk++) {
            float4 a0 = *(const float4*)(&As[kk][ty*8]);
            float4 a1 = *(const float4*)(&As[kk][ty*8+4]);
            float4 b0 = *(const float4*)(&Bs[kk][tx*8]);
            float4 b1 = *(const float4*)(&Bs[kk][tx*8+4]);
            float a[8] = {a0.x,a0.y,a0.z,a0.w,a1.x,a1.y,a1.z,a1.w};
            float bb[8] = {b0.x,b0.y,b0.z,b0.w,b1.x,b1.y,b1.z,b1.w};
            #pragma unroll
            for (int i = 0; i < 8; i++)
                #pragma unroll
                for (int j = 0; j < 8; j++)
                    acc[i][j] += a[i] * bb[j];
        }
        __syncthreads();
    }

    int mbase = bm*128 + ty*8;
    int nbase = bn*128 + tx*8;
    if (mode <= 1) {
        float* O = out;  // g_h region pointer passed in out
        #pragma unroll
        for (int i = 0; i < 8; i++) {
            int m = mbase + i;
            #pragma unroll
            for (int j = 0; j < 8; j++) {
                int n = nbase + j;
                O[(size_t)m * N + n] = fmaxf(acc[i][j] + bias[n], 0.f);
            }
        }
    } else {
        int branch_off = (mode == 2) ? 0 : (NBQ * VQn);   // 0 or 512
        // 128-wide N tile lies entirely within one v (768 % 128 == 0 pattern: tile of 128
        // never crosses a multiple-of-768 boundary since 768 = 6*128)
        #pragma unroll
        for (int i = 0; i < 8; i++) {
            int m = mbase + i;
            int b = m >> 6, q = m & 63;
            #pragma unroll
            for (int j = 0; j < 8; j++) {
                int n = nbase + j;
                int v = n / QHD, h = n - v * QHD;
                out[((size_t)(b*OUTROWS + branch_off + q*VQn + v)) * QHD + h] =
                    acc[i][j] + bias[n];
            }
        }
    }
}

// g_h write targets for modes 0/1 (device pointers can't be taken on host without
// symbol lookup; use a trampoline kernel argument-free approach instead: modes 0/1
// ignore 'out' being d_out-based and write to g_h directly)
__global__ void write_mask(const float* __restrict__ box_qmask,
                           const float* __restrict__ click_qmask,
                           float* __restrict__ out_mask) {
    int i = blockIdx.x * blockDim.x + threadIdx.x;
    if (i >= NB * OUTROWS) return;
    int b = i >> 10, r = i & 1023;
    float v = (r < NBQ*VQn) ? box_qmask[b*NBQ + (r >> 3)]
                            : click_qmask[b*NCK + ((r - NBQ*VQn) >> 3)];
    out_mask[i] = v;
}

// small helper kernels to fetch g_h base into epilogue targets is avoided:
// sgemm modes 0/1 must write g_h. We pass a dummy out pointer and redirect in-kernel.
__global__ __launch_bounds__(256, 2) void sgemm128_hidden(
        const float* __restrict__ W, const float* __restrict__ bias,
        int K, int mode) {
    // identical to sgemm128 modes 0/1 but writes g_h directly
    const float* A = (mode == 0) ? g_box_feat : g_click_in;
    float* O = (mode == 0) ? g_h : (g_h + (size_t)MROWS*QHD);
    const int N = QHD;

    __shared__ __align__(16) float As[8][128];
    __shared__ __align__(16) float Bs[8][128];

    int tid = threadIdx.x;
    int bm = blockIdx.y, bn = blockIdx.x;
    const float* Ab = A + (size_t)bm * 128 * K;
    const float* Wb = W + (size_t)bn * 128;

    int arow = tid >> 1, acol = (tid & 1) * 4;
    int brow = tid >> 5, bcol = (tid & 31) * 4;
    int ty = tid >> 4, tx = tid & 15;

    float acc[8][8];
    #pragma unroll
    for (int i = 0; i < 8; i++)
        #pragma unroll
        for (int j = 0; j < 8; j++) acc[i][j] = 0.f;

    for (int k0 = 0; k0 < K; k0 += 8) {
        float4 av = *(const float4*)(Ab + (size_t)arow * K + k0 + acol);
        As[acol+0][arow] = av.x; As[acol+1][arow] = av.y;
        As[acol+2][arow] = av.z; As[acol+3][arow] = av.w;
        float4 bv = *(const float4*)(Wb + (size_t)(k0 + brow) * N + bcol);
        *(float4*)(&Bs[brow][bcol]) = bv;
        __syncthreads();
        #pragma unroll
        for (int kk = 0; kk < 8; kk++) {
            float4 a0 = *(const float4*)(&As[kk][ty*8]);
            float4 a1 = *(const float4*)(&As[kk][ty*8+4]);
            float4 b0 = *(const float4*)(&Bs[kk][tx*8]);
            float4 b1 = *(const float4*)(&Bs[kk][tx*8+4]);
            float a[8] = {a0.x,a0.y,a0.z,a0.w,a1.x,a1.y,a1.z,a1.w};
            float bb[8] = {b0.x,b0.y,b0.z,b0.w,b1.x,b1.y,b1.z,b1.w};
            #pragma unroll
            for (int i = 0; i < 8; i++)
                #pragma unroll
                for (int j = 0; j < 8; j++)
                    acc[i][j] += a[i] * bb[j];
        }
        __syncthreads();
    }

    int mbase = bm*128 + ty*8;
    int nbase = bn*128 + tx*8;
    #pragma unroll
    for (int i = 0; i < 8; i++) {
        int m = mbase + i;
        #pragma unroll
        for (int j = 0; j < 8; j++) {
            int n = nbase + j;
            O[(size_t)m * N + n] = fmaxf(acc[i][j] + bias[n], 0.f);
        }
    }
}

extern "C" void kernel_launch(void* const* d_in, const int* in_sizes, int n_in,
                              void* d_out, int out_size) {
    const float* sem     = (const float*)d_in[0];
    const float* propf   = (const float*)d_in[1];
    const float* boxc    = (const float*)d_in[2];
    const float* encxyz  = (const float*)d_in[3];
    const float* encf    = (const float*)d_in[4];
    const float* pcmin   = (const float*)d_in[5];
    const float* pcmax   = (const float*)d_in[6];
    const float* boxq    = (const float*)d_in[7];
    const float* boxqm   = (const float*)d_in[8];
    const float* clickq  = (const float*)d_in[9];
    const float* clickqm = (const float*)d_in[10];
    const float* gauss   = (const float*)d_in[11];
    const float* bw1     = (const float*)d_in[12];
    const float* bb1     = (const float*)d_in[13];
    const float* bw2     = (const float*)d_in[14];
    const float* bb2     = (const float*)d_in[15];
    const float* cw1     = (const float*)d_in[16];
    const float* cb1     = (const float*)d_in[17];
    const float* cw2     = (const float*)d_in[18];
    const float* cb2     = (const float*)d_in[19];
    float* out = (float*)d_out;

    prop_prep<<<(NB*NPROP + 127)/128, 128>>>(sem, boxc);
    box_match<<<NB, 256>>>(boxq);
    gather_box<<<MROWS, 64>>>(propf);
    click_nn<<<NB, 256>>>(encxyz, clickq);
    click_build<<<MROWS, 128>>>(encf, clickq, pcmin, pcmax, gauss);

    // layer 1 (hidden, ReLU): M=2048, N=768
    {
        dim3 grid(QHD/128, MROWS/128);            // (6, 16)
        sgemm128_hidden<<<grid, 256>>>(bw1, bb1, CDIM, 0);
        sgemm128_hidden<<<grid, 256>>>(cw1, cb1, 2*CDIM, 1);
    }
    // layer 2 (output, reshape/concat fused): M=2048, N=6144
    {
        dim3 grid((VQn*QHD)/128, MROWS/128);       // (48, 16)
        sgemm128<<<grid, 256>>>(bw2, bb2, out, QHD, VQn*QHD, 2);
        sgemm128<<<grid, 256>>>(cw2, cb2, out, QHD, VQn*QHD, 3);
    }
    write_mask<<<(NB*OUTROWS + 255)/256, 256>>>(boxqm, clickqm, out + FEAT_ELEMS);
}

// round 5
// speedup vs baseline: 2.0378x; 2.0378x over previous
#include <cuda_runtime.h>
#include <cuda_bf16.h>
#include <math_constants.h>
#include <cstdint>

#define NB 32
#define NPROP 256
#define NCLS 19
#define NPTS 4096
#define NBQ 64
#define NCK 64
#define CDIM 256
#define QHD 768
#define VQn 8
#define MROWS (NB*NBQ)                 // 2048
#define OUTROWS 1024
#define FEAT_ELEMS (NB*OUTROWS*QHD)    // 25165824

// ================= device scratch =================
__device__ float g_mn[NB*NPROP*3];
__device__ float g_mx[NB*NPROP*3];
__device__ float g_vol[NB*NPROP];
__device__ float g_pmask[NB*NPROP];
__device__ int   g_match[MROWS];
__device__ int   g_nn[MROWS];

// split-bf16 operands (hi, lo)
__device__ __nv_bfloat16 g_bxA_h[MROWS*CDIM],   g_bxA_l[MROWS*CDIM];     // [2048,256]
__device__ __nv_bfloat16 g_ckA_h[MROWS*2*CDIM], g_ckA_l[MROWS*2*CDIM];   // [2048,512]
__device__ __nv_bfloat16 g_w1b_h[QHD*CDIM],     g_w1b_l[QHD*CDIM];       // [768,256]  (N,K)
__device__ __nv_bfloat16 g_w1c_h[QHD*2*CDIM],   g_w1c_l[QHD*2*CDIM];     // [768,512]
__device__ __nv_bfloat16 g_w2b_h[VQn*QHD*QHD],  g_w2b_l[VQn*QHD*QHD];    // [6144,768]
__device__ __nv_bfloat16 g_w2c_h[VQn*QHD*QHD],  g_w2c_l[VQn*QHD*QHD];    // [6144,768]
__device__ __nv_bfloat16 g_h1_h[MROWS*QHD],     g_h1_l[MROWS*QHD];       // box hidden
__device__ __nv_bfloat16 g_h2_h[MROWS*QHD],     g_h2_l[MROWS*QHD];       // click hidden

// ================= helpers =================
__device__ __forceinline__ uint32_t smem_u32(const void* p) {
    uint32_t a;
    asm("{ .reg .u64 t; cvta.to.shared.u64 t, %1; cvt.u32.u64 %0, t; }" : "=r"(a) : "l"(p));
    return a;
}
__device__ __forceinline__ void cp16(uint32_t dst, const void* src) {
    asm volatile("cp.async.cg.shared.global [%0], [%1], 16;" :: "r"(dst), "l"(src));
}
#define CP_COMMIT() asm volatile("cp.async.commit_group;" ::: "memory")
#define CP_WAIT1()  asm volatile("cp.async.wait_group 1;" ::: "memory")
#define CP_WAIT0()  asm volatile("cp.async.wait_group 0;" ::: "memory")

__device__ __forceinline__ void ldsm_x4(uint32_t* r, uint32_t addr) {
    asm volatile("ldmatrix.sync.aligned.m8n8.x4.shared.b16 {%0,%1,%2,%3}, [%4];"
        : "=r"(r[0]), "=r"(r[1]), "=r"(r[2]), "=r"(r[3]) : "r"(addr));
}
// NOTE: non-trans. B stored [N,K] row-major => consecutive-k contiguous, which is
// exactly the b-fragment register layout for mma row.col.
__device__ __forceinline__ void ldsm_x2(uint32_t* r, uint32_t addr) {
    asm volatile("ldmatrix.sync.aligned.m8n8.x2.shared.b16 {%0,%1}, [%2];"
        : "=r"(r[0]), "=r"(r[1]) : "r"(addr));
}
__device__ __forceinline__ void mma16816(float* d, const uint32_t* a, const uint32_t* b) {
    asm volatile(
        "mma.sync.aligned.m16n8k16.row.col.f32.bf16.bf16.f32 "
        "{%0,%1,%2,%3}, {%4,%5,%6,%7}, {%8,%9}, {%0,%1,%2,%3};"
        : "+f"(d[0]), "+f"(d[1]), "+f"(d[2]), "+f"(d[3])
        : "r"(a[0]), "r"(a[1]), "r"(a[2]), "r"(a[3]), "r"(b[0]), "r"(b[1]));
}
__device__ __forceinline__ void bsplit(float x, __nv_bfloat16* h, __nv_bfloat16* l) {
    __nv_bfloat16 hi = __float2bfloat16(x);
    *h = hi;
    *l = __float2bfloat16(x - __bfloat162float(hi));
}

// ================= prep kernels =================
__global__ void prop_prep(const float* __restrict__ logits, const float* __restrict__ corners) {
    int p = blockIdx.x * blockDim.x + threadIdx.x;
    if (p >= NB*NPROP) return;
    const float* l = logits + (size_t)p * NCLS;
    float best = l[0]; int bi = 0;
    #pragma unroll
    for (int k = 1; k < NCLS; k++) { float v = l[k]; if (v > best) { best = v; bi = k; } }
    g_pmask[p] = (bi != NCLS - 1) ? 1.f : 0.f;
    const float* cr = corners + (size_t)p * 24;
    float mn0 = cr[0], mn1 = cr[1], mn2 = cr[2];
    float mx0 = cr[0], mx1 = cr[1], mx2 = cr[2];
    #pragma unroll
    for (int c = 1; c < 8; c++) {
        float x = cr[c*3+0], y = cr[c*3+1], z = cr[c*3+2];
        mn0 = fminf(mn0, x); mx0 = fmaxf(mx0, x);
        mn1 = fminf(mn1, y); mx1 = fmaxf(mx1, y);
        mn2 = fminf(mn2, z); mx2 = fmaxf(mx2, z);
    }
    g_mn[p*3+0] = mn0; g_mn[p*3+1] = mn1; g_mn[p*3+2] = mn2;
    g_mx[p*3+0] = mx0; g_mx[p*3+1] = mx1; g_mx[p*3+2] = mx2;
    g_vol[p] = (mx0-mn0)*(mx1-mn1)*(mx2-mn2);
}

__global__ void box_match(const float* __restrict__ box_query) {
    __shared__ float s_mn[NPROP*3], s_mx[NPROP*3], s_vol[NPROP], s_msk[NPROP];
    int b = blockIdx.x, t = threadIdx.x;
    if (t < NPROP) {
        int p = b*NPROP + t;
        s_mn[t*3+0] = g_mn[p*3+0]; s_mn[t*3+1] = g_mn[p*3+1]; s_mn[t*3+2] = g_mn[p*3+2];
        s_mx[t*3+0] = g_mx[p*3+0]; s_mx[t*3+1] = g_mx[p*3+1]; s_mx[t*3+2] = g_mx[p*3+2];
        s_vol[t] = g_vol[p]; s_msk[t] = g_pmask[p];
    }
    __syncthreads();
    if (t < NBQ) {
        const float* cq = box_query + ((size_t)b*NBQ + t) * 24;
        float mn0 = cq[0], mn1 = cq[1], mn2 = cq[2];
        float mx0 = cq[0], mx1 = cq[1], mx2 = cq[2];
        #pragma unroll
        for (int c = 1; c < 8; c++) {
            float x = cq[c*3+0], y = cq[c*3+1], z = cq[c*3+2];
            mn0 = fminf(mn0, x); mx0 = fmaxf(mx0, x);
            mn1 = fminf(mn1, y); mx1 = fmaxf(mx1, y);
            mn2 = fminf(mn2, z); mx2 = fmaxf(mx2, z);
        }
        float volq = (mx0-mn0)*(mx1-mn1)*(mx2-mn2);
        float best = -1.f; int bi = 0;
        for (int p = 0; p < NPROP; p++) {
            float ix = fmaxf(fminf(mx0, s_mx[p*3+0]) - fmaxf(mn0, s_mn[p*3+0]), 0.f);
            float iy = fmaxf(fminf(mx1, s_mx[p*3+1]) - fmaxf(mn1, s_mn[p*3+1]), 0.f);
            float iz = fmaxf(fminf(mx2, s_mx[p*3+2]) - fmaxf(mn2, s_mn[p*3+2]), 0.f);
            float inter = ix*iy*iz;
            float iou = inter / (volq + s_vol[p] - inter + 1e-8f) * s_msk[p];
            if (iou > best) { best = iou; bi = p; }
        }
        g_match[b*NBQ + t] = bi;
    }
}

__global__ void gather_box(const float* __restrict__ prop_features) {
    int r = blockIdx.x;
    int b = r >> 6;
    int m = g_match[r];
    const float4* src = (const float4*)(prop_features + ((size_t)b*NPROP + m) * CDIM);
    float4 v = src[threadIdx.x];
    int o = r*CDIM + threadIdx.x*4;
    bsplit(v.x, &g_bxA_h[o+0], &g_bxA_l[o+0]);
    bsplit(v.y, &g_bxA_h[o+1], &g_bxA_l[o+1]);
    bsplit(v.z, &g_bxA_h[o+2], &g_bxA_l[o+2]);
    bsplit(v.w, &g_bxA_h[o+3], &g_bxA_l[o+3]);
}

__global__ void click_nn(const float* __restrict__ enc_xyz, const float* __restrict__ click_query) {
    __shared__ float s_xyz[NPTS*3];
    int b = blockIdx.x, t = threadIdx.x;
    const float* src = enc_xyz + (size_t)b * NPTS * 3;
    for (int i = t; i < NPTS*3; i += 256) s_xyz[i] = src[i];
    __syncthreads();
    int warp = t >> 5, lane = t & 31;
    for (int q = warp; q < NCK; q += 8) {
        const float* cq = click_query + ((size_t)b*NCK + q) * 3;
        float cx = cq[0], cy = cq[1], cz = cq[2];
        float best = CUDART_INF_F; int bi = 0;
        for (int p = lane; p < NPTS; p += 32) {
            float dx = cx - s_xyz[p*3+0];
            float dy = cy - s_xyz[p*3+1];
            float dz = cz - s_xyz[p*3+2];
            float d = dx*dx + dy*dy + dz*dz;
            if (d < best) { best = d; bi = p; }
        }
        #pragma unroll
        for (int off = 16; off; off >>= 1) {
            float ob = __shfl_xor_sync(0xffffffffu, best, off);
            int   oi = __shfl_xor_sync(0xffffffffu, bi, off);
            if (ob < best || (ob == best && oi < bi)) { best = ob; bi = oi; }
        }
        if (lane == 0) g_nn[b*NCK + q] = bi;
    }
}

__global__ void click_build(const float* __restrict__ enc_features,
                            const float* __restrict__ click_query,
                            const float* __restrict__ pc_min,
                            const float* __restrict__ pc_max,
                            const float* __restrict__ gauss) {
    int r = blockIdx.x, t = threadIdx.x;  // 128 threads
    int b = r >> 6;
    int nn = g_nn[r];
    const float2* src = (const float2*)(enc_features + ((size_t)b*NPTS + nn) * CDIM);
    float2 v = src[t];
    int o = r*2*CDIM + 2*t;
    bsplit(v.x, &g_ckA_h[o+0], &g_ckA_l[o+0]);
    bsplit(v.y, &g_ckA_h[o+1], &g_ckA_l[o+1]);
    const float* cq = click_query + (size_t)r * 3;
    float pr = 0.f;
    #pragma unroll
    for (int d = 0; d < 3; d++) {
        float x01 = (cq[d] - pc_min[b*3+d]) / (pc_max[b*3+d] - pc_min[b*3+d]);
        pr += x01 * 6.283185307179586f * gauss[d*(CDIM/2) + t];
    }
    int ps  = r*2*CDIM + CDIM + t;
    int pcs = r*2*CDIM + CDIM + 128 + t;
    bsplit(sinf(pr), &g_ckA_h[ps],  &g_ckA_l[ps]);
    bsplit(cosf(pr), &g_ckA_h[pcs], &g_ckA_l[pcs]);
}

// transpose + split-convert: src [K,N] f32 -> dst [N,K] bf16 hi/lo
__global__ void tconv(const float* __restrict__ src,
                      __nv_bfloat16* __restrict__ dh, __nv_bfloat16* __restrict__ dl,
                      int K, int N) {
    __shared__ float tile[32][33];
    int n0 = blockIdx.x*32, k0 = blockIdx.y*32;
    int tx = threadIdx.x, ty = threadIdx.y;
    #pragma unroll
    for (int j = 0; j < 4; j++)
        tile[ty + 8*j][tx] = src[(size_t)(k0 + ty + 8*j) * N + n0 + tx];
    __syncthreads();
    #pragma unroll
    for (int j = 0; j < 4; j++) {
        float v = tile[tx][ty + 8*j];
        size_t o = (size_t)(n0 + ty + 8*j) * K + k0 + tx;
        bsplit(v, &dh[o], &dl[o]);
    }
}

// ================= HMMA split-bf16 GEMM =================
// 128x128 CTA tile, BK=32, 8 warps (2M x 4N), warp tile 64x32.
// A [M,K] bf16 hi/lo row-major; B [N,K] bf16 hi/lo row-major.
// D = Ah*Bh + Al*Bh + Ah*Bl  (fp32 accum)
// mode 0: relu(D+bias) -> split Hh/Hl; mode 1/2: D+bias -> out remapped.
#define ROWB 80                      // padded row stride bytes (32 bf16 -> 80B)
#define TILE_B (128*ROWB)            // 10240
#define STAGE_B (4*TILE_B)           // 40960
#define SMEM_NEED (2*STAGE_B + 512)  // 82432

__global__ __launch_bounds__(256, 1)
void tgemm(const __nv_bfloat16* __restrict__ Ah, const __nv_bfloat16* __restrict__ Al,
           const __nv_bfloat16* __restrict__ Bh, const __nv_bfloat16* __restrict__ Bl,
           const float* __restrict__ bias,
           float* __restrict__ outf,
           __nv_bfloat16* __restrict__ Hh, __nv_bfloat16* __restrict__ Hl,
           int K, int mode) {
    extern __shared__ __align__(16) char smem_raw[];
    const uint32_t base = smem_u32(smem_raw);
    float* s_bias = (float*)(smem_raw + 2*STAGE_B);

    const int t = threadIdx.x;
    const int wid = t >> 5, lid = t & 31;
    const int mwarp = wid & 1, nwarp = wid >> 1;
    const int m0 = blockIdx.y * 128;
    const int n0 = blockIdx.x * 128;
    const int S = K >> 5;            // K-slabs of 32

    if (t < 128) s_bias[t] = bias[n0 + t];

    float acc[4][4][4];
    #pragma unroll
    for (int mi = 0; mi < 4; mi++)
        #pragma unroll
        for (int ni = 0; ni < 4; ni++)
            #pragma unroll
            for (int r = 0; r < 4; r++) acc[mi][ni][r] = 0.f;

    auto load_slab = [&](int s, int st) {
        uint32_t sb = base + st * STAGE_B;
        size_t kof = (size_t)s * 32;
        #pragma unroll
        for (int i = 0; i < 8; i++) {
            int c = i * 256 + t;              // 0..2047
            int tile = c >> 9, local = c & 511;
            int row = local >> 2, chk = local & 3;
            uint32_t dst = sb + tile * TILE_B + row * ROWB + chk * 16;
            const __nv_bfloat16* srcp;
            if      (tile == 0) srcp = Ah + (size_t)(m0 + row) * K + kof + chk * 8;
            else if (tile == 1) srcp = Al + (size_t)(m0 + row) * K + kof + chk * 8;
            else if (tile == 2) srcp = Bh + (size_t)(n0 + row) * K + kof + chk * 8;
            else                srcp = Bl + (size_t)(n0 + row) * K + kof + chk * 8;
            cp16(dst, srcp);
        }
    };

    auto compute_stage = [&](int st) {
        uint32_t sb = base + st * STAGE_B;
        uint32_t aH = sb, aL = sb + TILE_B, bH = sb + 2*TILE_B, bL = sb + 3*TILE_B;
        #pragma unroll
        for (int ks = 0; ks < 32; ks += 16) {
            uint32_t ah[4][4], al[4][4], bh[4][2], bl[4][2];
            uint32_t aoff = (uint32_t)((mwarp*64 + (lid & 15)) * ROWB
                                       + (ks + ((lid >> 4) << 3)) * 2);
            #pragma unroll
            for (int mi = 0; mi < 4; mi++) {
                ldsm_x4(ah[mi], aH + aoff + mi*16*ROWB);
                ldsm_x4(al[mi], aL + aoff + mi*16*ROWB);
            }
            uint32_t boff = (uint32_t)((nwarp*32 + (lid & 7)) * ROWB
                                       + (ks + (((lid >> 3) & 1) << 3)) * 2);
            #pragma unroll
            for (int ni = 0; ni < 4; ni++) {
                ldsm_x2(bh[ni], bH + boff + ni*8*ROWB);
                ldsm_x2(bl[ni], bL + boff + ni*8*ROWB);
            }
            #pragma unroll
            for (int mi = 0; mi < 4; mi++)
                #pragma unroll
                for (int ni = 0; ni < 4; ni++) {
                    mma16816(acc[mi][ni], ah[mi], bh[ni]);
                    mma16816(acc[mi][ni], al[mi], bh[ni]);
                    mma16816(acc[mi][ni], ah[mi], bl[ni]);
                }
        }
    };

    load_slab(0, 0);
    CP_COMMIT();
    for (int s = 0; s < S; s++) {
        if (s + 1 < S) { load_slab(s + 1, (s + 1) & 1); CP_COMMIT(); CP_WAIT1(); }
        else           { CP_WAIT0(); }
        __syncthreads();
        compute_stage(s & 1);
        __syncthreads();
    }

    // epilogue
    const int mb = m0 + mwarp*64;
    const int nb = n0 + nwarp*32;
    #pragma unroll
    for (int mi = 0; mi < 4; mi++) {
        int r0 = mb + mi*16 + (lid >> 2);
        #pragma unroll
        for (int ni = 0; ni < 4; ni++) {
            int n = nb + ni*8 + (lid & 3)*2;
            float v00 = acc[mi][ni][0] + s_bias[n   - n0];
            float v01 = acc[mi][ni][1] + s_bias[n+1 - n0];
            float v10 = acc[mi][ni][2] + s_bias[n   - n0];
            float v11 = acc[mi][ni][3] + s_bias[n+1 - n0];
            if (mode == 0) {
                v00 = fmaxf(v00, 0.f); v01 = fmaxf(v01, 0.f);
                v10 = fmaxf(v10, 0.f); v11 = fmaxf(v11, 0.f);
                size_t o0 = (size_t)r0 * QHD + n;
                size_t o1 = (size_t)(r0 + 8) * QHD + n;
                bsplit(v00, &Hh[o0],   &Hl[o0]);
                bsplit(v01, &Hh[o0+1], &Hl[o0+1]);
                bsplit(v10, &Hh[o1],   &Hl[o1]);
                bsplit(v11, &Hh[o1+1], &Hl[o1+1]);
            } else {
                int boff = (mode == 1) ? 0 : (NBQ * VQn);
                int vq = n / QHD, h = n - vq * QHD;   // n, n+1 same vq
                int b0 = r0 >> 6, q0 = r0 & 63;
                int r1 = r0 + 8;
                int b1 = r1 >> 6, q1 = r1 & 63;
                size_t o0 = ((size_t)(b0*OUTROWS + boff + q0*VQn + vq)) * QHD + h;
                size_t o1 = ((size_t)(b1*OUTROWS + boff + q1*VQn + vq)) * QHD + h;
                outf[o0]   = v00; outf[o0+1] = v01;
                outf[o1]   = v10; outf[o1+1] = v11;
            }
        }
    }
}

__global__ void write_mask(const float* __restrict__ box_qmask,
                           const float* __restrict__ click_qmask,
                           float* __restrict__ out_mask) {
    int i = blockIdx.x * blockDim.x + threadIdx.x;
    if (i >= NB * OUTROWS) return;
    int b = i >> 10, r = i & 1023;
    float v = (r < NBQ*VQn) ? box_qmask[b*NBQ + (r >> 3)]
                            : click_qmask[b*NCK + ((r - NBQ*VQn) >> 3)];
    out_mask[i] = v;
}

// ================= host =================
extern "C" void kernel_launch(void* const* d_in, const int* in_sizes, int n_in,
                              void* d_out, int out_size) {
    const float* sem     = (const float*)d_in[0];
    const float* propf   = (const float*)d_in[1];
    const float* boxc    = (const float*)d_in[2];
    const float* encxyz  = (const float*)d_in[3];
    const float* encf    = (const float*)d_in[4];
    const float* pcmin   = (const float*)d_in[5];
    const float* pcmax   = (const float*)d_in[6];
    const float* boxq    = (const float*)d_in[7];
    const float* boxqm   = (const float*)d_in[8];
    const float* clickq  = (const float*)d_in[9];
    const float* clickqm = (const float*)d_in[10];
    const float* gauss   = (const float*)d_in[11];
    const float* bw1     = (const float*)d_in[12];
    const float* bb1     = (const float*)d_in[13];
    const float* bw2     = (const float*)d_in[14];
    const float* bb2     = (const float*)d_in[15];
    const float* cw1     = (const float*)d_in[16];
    const float* cb1     = (const float*)d_in[17];
    const float* cw2     = (const float*)d_in[18];
    const float* cb2     = (const float*)d_in[19];
    float* out = (float*)d_out;

    void *bxh, *bxl, *ckh, *ckl, *w1bh, *w1bl, *w1ch, *w1cl,
         *w2bh, *w2bl, *w2ch, *w2cl, *h1h, *h1l, *h2h, *h2l;
    cudaGetSymbolAddress(&bxh,  g_bxA_h); cudaGetSymbolAddress(&bxl,  g_bxA_l);
    cudaGetSymbolAddress(&ckh,  g_ckA_h); cudaGetSymbolAddress(&ckl,  g_ckA_l);
    cudaGetSymbolAddress(&w1bh, g_w1b_h); cudaGetSymbolAddress(&w1bl, g_w1b_l);
    cudaGetSymbolAddress(&w1ch, g_w1c_h); cudaGetSymbolAddress(&w1cl, g_w1c_l);
    cudaGetSymbolAddress(&w2bh, g_w2b_h); cudaGetSymbolAddress(&w2bl, g_w2b_l);
    cudaGetSymbolAddress(&w2ch, g_w2c_h); cudaGetSymbolAddress(&w2cl, g_w2c_l);
    cudaGetSymbolAddress(&h1h,  g_h1_h);  cudaGetSymbolAddress(&h1l,  g_h1_l);
    cudaGetSymbolAddress(&h2h,  g_h2_h);  cudaGetSymbolAddress(&h2l,  g_h2_l);

    cudaFuncSetAttribute(tgemm, cudaFuncAttributeMaxDynamicSharedMemorySize, SMEM_NEED);

    prop_prep<<<(NB*NPROP + 127)/128, 128>>>(sem, boxc);
    box_match<<<NB, 256>>>(boxq);
    gather_box<<<MROWS, 64>>>(propf);
    click_nn<<<NB, 256>>>(encxyz, clickq);
    click_build<<<MROWS, 128>>>(encf, clickq, pcmin, pcmax, gauss);

    {
        dim3 blk(32, 8);
        tconv<<<dim3(QHD/32, CDIM/32),    blk>>>(bw1, (__nv_bfloat16*)w1bh, (__nv_bfloat16*)w1bl, CDIM,   QHD);
        tconv<<<dim3(QHD/32, 2*CDIM/32),  blk>>>(cw1, (__nv_bfloat16*)w1ch, (__nv_bfloat16*)w1cl, 2*CDIM, QHD);
        tconv<<<dim3(VQn*QHD/32, QHD/32), blk>>>(bw2, (__nv_bfloat16*)w2bh, (__nv_bfloat16*)w2bl, QHD, VQn*QHD);
        tconv<<<dim3(VQn*QHD/32, QHD/32), blk>>>(cw2, (__nv_bfloat16*)w2ch, (__nv_bfloat16*)w2cl, QHD, VQn*QHD);
    }

    // layer 1: M=2048, N=768 -> hidden split
    {
        dim3 grid(QHD/128, MROWS/128);  // (6,16)
        tgemm<<<grid, 256, SMEM_NEED>>>((__nv_bfloat16*)bxh, (__nv_bfloat16*)bxl,
                                        (__nv_bfloat16*)w1bh, (__nv_bfloat16*)w1bl,
                                        bb1, out, (__nv_bfloat16*)h1h, (__nv_bfloat16*)h1l,
                                        CDIM, 0);
        tgemm<<<grid, 256, SMEM_NEED>>>((__nv_bfloat16*)ckh, (__nv_bfloat16*)ckl,
                                        (__nv_bfloat16*)w1ch, (__nv_bfloat16*)w1cl,
                                        cb1, out, (__nv_bfloat16*)h2h, (__nv_bfloat16*)h2l,
                                        2*CDIM, 0);
    }
    // layer 2: M=2048, N=6144 -> out (remapped)
    {
        dim3 grid(VQn*QHD/128, MROWS/128);  // (48,16)
        tgemm<<<grid, 256, SMEM_NEED>>>((__nv_bfloat16*)h1h, (__nv_bfloat16*)h1l,
                                        (__nv_bfloat16*)w2bh, (__nv_bfloat16*)w2bl,
                                        bb2, out, nullptr, nullptr, QHD, 1);
        tgemm<<<grid, 256, SMEM_NEED>>>((__nv_bfloat16*)h2h, (__nv_bfloat16*)h2l,
                                        (__nv_bfloat16*)w2ch, (__nv_bfloat16*)w2cl,
                                        cb2, out, nullptr, nullptr, QHD, 2);
    }
    write_mask<<<(NB*OUTROWS + 255)/256, 256>>>(boxqm, clickqm, out + FEAT_ELEMS);
}

// round 6
// speedup vs baseline: 2.8137x; 1.3808x over previous
#include <cuda_runtime.h>
#include <cuda_fp16.h>
#include <math_constants.h>
#include <cstdint>

#define NB 32
#define NPROP 256
#define NCLS 19
#define NPTS 4096
#define NBQ 64
#define NCK 64
#define CDIM 256
#define QHD 768
#define VQn 8
#define MROWS (NB*NBQ)                 // 2048
#define OUTROWS 1024
#define FEAT_ELEMS (NB*OUTROWS*QHD)    // 25165824

// ================= device scratch =================
__device__ float g_mn[NB*NPROP*3];
__device__ float g_mx[NB*NPROP*3];
__device__ float g_vol[NB*NPROP];
__device__ float g_pmask[NB*NPROP];
__device__ int   g_match[MROWS];
__device__ unsigned long long g_nnpack[MROWS];

// fp16 operands: A-side split hi/lo (exact to ~2^-22), B-side (weights) hi only
__device__ __half g_bxA_h[MROWS*CDIM],   g_bxA_l[MROWS*CDIM];     // [2048,256]
__device__ __half g_ckA_h[MROWS*2*CDIM], g_ckA_l[MROWS*2*CDIM];   // [2048,512]
__device__ __half g_w1b_h[QHD*CDIM];                              // [768,256]  (N,K)
__device__ __half g_w1c_h[QHD*2*CDIM];                            // [768,512]
__device__ __half g_w2b_h[VQn*QHD*QHD];                           // [6144,768]
__device__ __half g_w2c_h[VQn*QHD*QHD];                           // [6144,768]
__device__ __half g_h1_h[MROWS*QHD], g_h1_l[MROWS*QHD];           // box hidden
__device__ __half g_h2_h[MROWS*QHD], g_h2_l[MROWS*QHD];           // click hidden

// ================= helpers =================
__device__ __forceinline__ uint32_t smem_u32(const void* p) {
    uint32_t a;
    asm("{ .reg .u64 t; cvta.to.shared.u64 t, %1; cvt.u32.u64 %0, t; }" : "=r"(a) : "l"(p));
    return a;
}
__device__ __forceinline__ void cp16(uint32_t dst, const void* src) {
    asm volatile("cp.async.cg.shared.global [%0], [%1], 16;" :: "r"(dst), "l"(src));
}
#define CP_COMMIT() asm volatile("cp.async.commit_group;" ::: "memory")
#define CP_WAIT1()  asm volatile("cp.async.wait_group 1;" ::: "memory")
#define CP_WAIT0()  asm volatile("cp.async.wait_group 0;" ::: "memory")

__device__ __forceinline__ void ldsm_x4(uint32_t* r, uint32_t addr) {
    asm volatile("ldmatrix.sync.aligned.m8n8.x4.shared.b16 {%0,%1,%2,%3}, [%4];"
        : "=r"(r[0]), "=r"(r[1]), "=r"(r[2]), "=r"(r[3]) : "r"(addr));
}
__device__ __forceinline__ void ldsm_x2(uint32_t* r, uint32_t addr) {
    asm volatile("ldmatrix.sync.aligned.m8n8.x2.shared.b16 {%0,%1}, [%2];"
        : "=r"(r[0]), "=r"(r[1]) : "r"(addr));
}
__device__ __forceinline__ void mma16816(float* d, const uint32_t* a, const uint32_t* b) {
    asm volatile(
        "mma.sync.aligned.m16n8k16.row.col.f32.f16.f16.f32 "
        "{%0,%1,%2,%3}, {%4,%5,%6,%7}, {%8,%9}, {%0,%1,%2,%3};"
        : "+f"(d[0]), "+f"(d[1]), "+f"(d[2]), "+f"(d[3])
        : "r"(a[0]), "r"(a[1]), "r"(a[2]), "r"(a[3]), "r"(b[0]), "r"(b[1]));
}
__device__ __forceinline__ void hsplit(float x, __half* h, __half* l) {
    __half hi = __float2half_rn(x);
    *h = hi;
    *l = __float2half_rn(x - __half2float(hi));
}

// ================= prep kernels =================
__global__ void prop_prep(const float* __restrict__ logits, const float* __restrict__ corners) {
    int p = blockIdx.x * blockDim.x + threadIdx.x;
    if (p >= NB*NPROP) return;
    const float* l = logits + (size_t)p * NCLS;
    float best = l[0]; int bi = 0;
    #pragma unroll
    for (int k = 1; k < NCLS; k++) { float v = l[k]; if (v > best) { best = v; bi = k; } }
    g_pmask[p] = (bi != NCLS - 1) ? 1.f : 0.f;
    const float* cr = corners + (size_t)p * 24;
    float mn0 = cr[0], mn1 = cr[1], mn2 = cr[2];
    float mx0 = cr[0], mx1 = cr[1], mx2 = cr[2];
    #pragma unroll
    for (int c = 1; c < 8; c++) {
        float x = cr[c*3+0], y = cr[c*3+1], z = cr[c*3+2];
        mn0 = fminf(mn0, x); mx0 = fmaxf(mx0, x);
        mn1 = fminf(mn1, y); mx1 = fmaxf(mx1, y);
        mn2 = fminf(mn2, z); mx2 = fmaxf(mx2, z);
    }
    g_mn[p*3+0] = mn0; g_mn[p*3+1] = mn1; g_mn[p*3+2] = mn2;
    g_mx[p*3+0] = mx0; g_mx[p*3+1] = mx1; g_mx[p*3+2] = mx2;
    g_vol[p] = (mx0-mn0)*(mx1-mn1)*(mx2-mn2);
}

__global__ void nn_init() {
    int i = blockIdx.x * blockDim.x + threadIdx.x;
    if (i < MROWS) g_nnpack[i] = ~0ull;
}

__global__ void box_match(const float* __restrict__ box_query) {
    __shared__ float s_mn[NPROP*3], s_mx[NPROP*3], s_vol[NPROP], s_msk[NPROP];
    int b = blockIdx.x, t = threadIdx.x;
    if (t < NPROP) {
        int p = b*NPROP + t;
        s_mn[t*3+0] = g_mn[p*3+0]; s_mn[t*3+1] = g_mn[p*3+1]; s_mn[t*3+2] = g_mn[p*3+2];
        s_mx[t*3+0] = g_mx[p*3+0]; s_mx[t*3+1] = g_mx[p*3+1]; s_mx[t*3+2] = g_mx[p*3+2];
        s_vol[t] = g_vol[p]; s_msk[t] = g_pmask[p];
    }
    __syncthreads();
    if (t < NBQ) {
        const float* cq = box_query + ((size_t)b*NBQ + t) * 24;
        float mn0 = cq[0], mn1 = cq[1], mn2 = cq[2];
        float mx0 = cq[0], mx1 = cq[1], mx2 = cq[2];
        #pragma unroll
        for (int c = 1; c < 8; c++) {
            float x = cq[c*3+0], y = cq[c*3+1], z = cq[c*3+2];
            mn0 = fminf(mn0, x); mx0 = fmaxf(mx0, x);
            mn1 = fminf(mn1, y); mx1 = fmaxf(mx1, y);
            mn2 = fminf(mn2, z); mx2 = fmaxf(mx2, z);
        }
        float volq = (mx0-mn0)*(mx1-mn1)*(mx2-mn2);
        float best = -1.f; int bi = 0;
        for (int p = 0; p < NPROP; p++) {
            float ix = fmaxf(fminf(mx0, s_mx[p*3+0]) - fmaxf(mn0, s_mn[p*3+0]), 0.f);
            float iy = fmaxf(fminf(mx1, s_mx[p*3+1]) - fmaxf(mn1, s_mn[p*3+1]), 0.f);
            float iz = fmaxf(fminf(mx2, s_mx[p*3+2]) - fmaxf(mn2, s_mn[p*3+2]), 0.f);
            float inter = ix*iy*iz;
            float iou = inter / (volq + s_vol[p] - inter + 1e-8f) * s_msk[p];
            if (iou > best) { best = iou; bi = p; }
        }
        g_match[b*NBQ + t] = bi;
    }
}

__global__ void gather_box(const float* __restrict__ prop_features) {
    int r = blockIdx.x;
    int b = r >> 6;
    int m = g_match[r];
    const float4* src = (const float4*)(prop_features + ((size_t)b*NPROP + m) * CDIM);
    float4 v = src[threadIdx.x];
    int o = r*CDIM + threadIdx.x*4;
    hsplit(v.x, &g_bxA_h[o+0], &g_bxA_l[o+0]);
    hsplit(v.y, &g_bxA_h[o+1], &g_bxA_l[o+1]);
    hsplit(v.z, &g_bxA_h[o+2], &g_bxA_l[o+2]);
    hsplit(v.w, &g_bxA_h[o+3], &g_bxA_l[o+3]);
}

// grid (NB, 8): each block handles 512 points for all 64 queries; atomicMin merge.
#define NN_PTS 512
__global__ void click_nn(const float* __restrict__ enc_xyz, const float* __restrict__ click_query) {
    __shared__ float s_xyz[NN_PTS*3];
    int b = blockIdx.x, ck = blockIdx.y, t = threadIdx.x;
    const float* src = enc_xyz + ((size_t)b*NPTS + ck*NN_PTS) * 3;
    for (int i = t; i < NN_PTS*3; i += 256) s_xyz[i] = src[i];
    __syncthreads();
    int warp = t >> 5, lane = t & 31;
    for (int q = warp; q < NCK; q += 8) {
        const float* cq = click_query + ((size_t)b*NCK + q) * 3;
        float cx = cq[0], cy = cq[1], cz = cq[2];
        float best = CUDART_INF_F; int bi = 0;
        for (int p = lane; p < NN_PTS; p += 32) {
            float dx = cx - s_xyz[p*3+0];
            float dy = cy - s_xyz[p*3+1];
            float dz = cz - s_xyz[p*3+2];
            float d = dx*dx + dy*dy + dz*dz;
            if (d < best) { best = d; bi = p; }
        }
        #pragma unroll
        for (int off = 16; off; off >>= 1) {
            float ob = __shfl_xor_sync(0xffffffffu, best, off);
            int   oi = __shfl_xor_sync(0xffffffffu, bi, off);
            if (ob < best || (ob == best && oi < bi)) { best = ob; bi = oi; }
        }
        if (lane == 0) {
            unsigned long long key = ((unsigned long long)__float_as_uint(best) << 32)
                                   | (unsigned)(ck*NN_PTS + bi);
            atomicMin(&g_nnpack[b*NCK + q], key);
        }
    }
}

__global__ void click_build(const float* __restrict__ enc_features,
                            const float* __restrict__ click_query,
                            const float* __restrict__ pc_min,
                            const float* __restrict__ pc_max,
                            const float* __restrict__ gauss) {
    int r = blockIdx.x, t = threadIdx.x;  // 128 threads
    int b = r >> 6;
    int nn = (int)(g_nnpack[r] & 0xffffffffull);
    const float2* src = (const float2*)(enc_features + ((size_t)b*NPTS + nn) * CDIM);
    float2 v = src[t];
    int o = r*2*CDIM + 2*t;
    hsplit(v.x, &g_ckA_h[o+0], &g_ckA_l[o+0]);
    hsplit(v.y, &g_ckA_h[o+1], &g_ckA_l[o+1]);
    const float* cq = click_query + (size_t)r * 3;
    float pr = 0.f;
    #pragma unroll
    for (int d = 0; d < 3; d++) {
        float x01 = (cq[d] - pc_min[b*3+d]) / (pc_max[b*3+d] - pc_min[b*3+d]);
        pr += x01 * 6.283185307179586f * gauss[d*(CDIM/2) + t];
    }
    int ps  = r*2*CDIM + CDIM + t;
    int pcs = r*2*CDIM + CDIM + 128 + t;
    hsplit(sinf(pr), &g_ckA_h[ps],  &g_ckA_l[ps]);
    hsplit(cosf(pr), &g_ckA_h[pcs], &g_ckA_l[pcs]);
}

// transpose + fp16 convert: src [K,N] f32 -> dst [N,K] fp16
__global__ void tconv(const float* __restrict__ src, __half* __restrict__ dh, int K, int N) {
    __shared__ float tile[32][33];
    int n0 = blockIdx.x*32, k0 = blockIdx.y*32;
    int tx = threadIdx.x, ty = threadIdx.y;
    #pragma unroll
    for (int j = 0; j < 4; j++)
        tile[ty + 8*j][tx] = src[(size_t)(k0 + ty + 8*j) * N + n0 + tx];
    __syncthreads();
    #pragma unroll
    for (int j = 0; j < 4; j++)
        dh[(size_t)(n0 + ty + 8*j) * K + k0 + tx] = __float2half_rn(tile[tx][ty + 8*j]);
}

// ================= HMMA fp16-split GEMM =================
// 128x128 CTA tile, BK=32, 8 warps (2M x 4N), warp tile 64x32.
// A [M,K] fp16 hi/lo row-major; B [N,K] fp16 row-major.
// D = Ah*Bh + Al*Bh = A_exact * B_fp16  (fp32 accum)
#define ROWB 80                      // padded row stride (32 fp16 -> 80B, conflict-free)
#define TILE_B (128*ROWB)            // 10240
#define STAGE_B (3*TILE_B)           // 30720 (Ah, Al, Bh)
#define SMEM_NEED (2*STAGE_B + 512)  // 61952

__device__ __forceinline__ void gemm_body(
        const __half* __restrict__ Ah, const __half* __restrict__ Al,
        const __half* __restrict__ Bh,
        int K, int m0, int n0, uint32_t base, int t, float acc[4][4][4]) {
    const int lid = t & 31;
    const int mwarp = (t >> 5) & 1, nwarp = t >> 6;
    const int S = K >> 5;

    auto load_slab = [&](int s, int st) {
        uint32_t sb = base + st * STAGE_B;
        size_t kof = (size_t)s * 32;
        #pragma unroll
        for (int i = 0; i < 6; i++) {
            int c = i * 256 + t;              // 0..1535
            int tile = c >> 9, local = c & 511;
            int row = local >> 2, chk = local & 3;
            uint32_t dst = sb + tile * TILE_B + row * ROWB + chk * 16;
            const __half* srcp;
            if      (tile == 0) srcp = Ah + (size_t)(m0 + row) * K + kof + chk * 8;
            else if (tile == 1) srcp = Al + (size_t)(m0 + row) * K + kof + chk * 8;
            else                srcp = Bh + (size_t)(n0 + row) * K + kof + chk * 8;
            cp16(dst, srcp);
        }
    };

    auto compute_stage = [&](int st) {
        uint32_t sb = base + st * STAGE_B;
        uint32_t aH = sb, aL = sb + TILE_B, bH = sb + 2*TILE_B;
        #pragma unroll
        for (int ks = 0; ks < 32; ks += 16) {
            uint32_t ah[4][4], al[4][4], bh[4][2];
            uint32_t aoff = (uint32_t)((mwarp*64 + (lid & 15)) * ROWB
                                       + (ks + ((lid >> 4) << 3)) * 2);
            #pragma unroll
            for (int mi = 0; mi < 4; mi++) {
                ldsm_x4(ah[mi], aH + aoff + mi*16*ROWB);
                ldsm_x4(al[mi], aL + aoff + mi*16*ROWB);
            }
            uint32_t boff = (uint32_t)((nwarp*32 + (lid & 7)) * ROWB
                                       + (ks + (((lid >> 3) & 1) << 3)) * 2);
            #pragma unroll
            for (int ni = 0; ni < 4; ni++)
                ldsm_x2(bh[ni], bH + boff + ni*8*ROWB);
            #pragma unroll
            for (int mi = 0; mi < 4; mi++)
                #pragma unroll
                for (int ni = 0; ni < 4; ni++) {
                    mma16816(acc[mi][ni], ah[mi], bh[ni]);
                    mma16816(acc[mi][ni], al[mi], bh[ni]);
                }
        }
    };

    load_slab(0, 0);
    CP_COMMIT();
    for (int s = 0; s < S; s++) {
        if (s + 1 < S) { load_slab(s + 1, (s + 1) & 1); CP_COMMIT(); CP_WAIT1(); }
        else           { CP_WAIT0(); }
        __syncthreads();
        compute_stage(s & 1);
        __syncthreads();
    }
}

// layer 1 (both branches via blockIdx.z): relu(D+bias) -> fp16 split hidden
__global__ __launch_bounds__(256, 1) void tgemm_l1(
        const __half* Ah0, const __half* Al0, const __half* Bh0, const float* b0, int K0,
        __half* Hh0, __half* Hl0,
        const __half* Ah1, const __half* Al1, const __half* Bh1, const float* b1, int K1,
        __half* Hh1, __half* Hl1) {
    extern __shared__ __align__(16) char smem_raw[];
    const uint32_t base = smem_u32(smem_raw);
    float* s_bias = (float*)(smem_raw + 2*STAGE_B);
    int z = blockIdx.z, t = threadIdx.x;
    const __half* Ah = z ? Ah1 : Ah0;
    const __half* Al = z ? Al1 : Al0;
    const __half* Bh = z ? Bh1 : Bh0;
    const float* bias = z ? b1 : b0;
    int K = z ? K1 : K0;
    __half* Hh = z ? Hh1 : Hh0;
    __half* Hl = z ? Hl1 : Hl0;
    int m0 = blockIdx.y * 128, n0 = blockIdx.x * 128;
    if (t < 128) s_bias[t] = bias[n0 + t];

    float acc[4][4][4];
    #pragma unroll
    for (int mi = 0; mi < 4; mi++)
        #pragma unroll
        for (int ni = 0; ni < 4; ni++)
            #pragma unroll
            for (int r = 0; r < 4; r++) acc[mi][ni][r] = 0.f;

    gemm_body(Ah, Al, Bh, K, m0, n0, base, t, acc);

    const int lid = t & 31;
    const int mb = m0 + ((t >> 5) & 1) * 64;
    const int nb = n0 + (t >> 6) * 32;
    #pragma unroll
    for (int mi = 0; mi < 4; mi++) {
        int r0 = mb + mi*16 + (lid >> 2);
        #pragma unroll
        for (int ni = 0; ni < 4; ni++) {
            int n = nb + ni*8 + (lid & 3)*2;
            float v00 = fmaxf(acc[mi][ni][0] + s_bias[n   - n0], 0.f);
            float v01 = fmaxf(acc[mi][ni][1] + s_bias[n+1 - n0], 0.f);
            float v10 = fmaxf(acc[mi][ni][2] + s_bias[n   - n0], 0.f);
            float v11 = fmaxf(acc[mi][ni][3] + s_bias[n+1 - n0], 0.f);
            size_t o0 = (size_t)r0 * QHD + n;
            size_t o1 = (size_t)(r0 + 8) * QHD + n;
            hsplit(v00, &Hh[o0],   &Hl[o0]);
            hsplit(v01, &Hh[o0+1], &Hl[o0+1]);
            hsplit(v10, &Hh[o1],   &Hl[o1]);
            hsplit(v11, &Hh[o1+1], &Hl[o1+1]);
        }
    }
}

// layer 2 (both branches via blockIdx.z): D+bias -> out remapped (b,q,v,h)
__global__ __launch_bounds__(256, 1) void tgemm_l2(
        const __half* Ah0, const __half* Al0, const __half* Bh0, const float* b0,
        const __half* Ah1, const __half* Al1, const __half* Bh1, const float* b1,
        float* __restrict__ outf) {
    extern __shared__ __align__(16) char smem_raw[];
    const uint32_t base = smem_u32(smem_raw);
    float* s_bias = (float*)(smem_raw + 2*STAGE_B);
    int z = blockIdx.z, t = threadIdx.x;
    const __half* Ah = z ? Ah1 : Ah0;
    const __half* Al = z ? Al1 : Al0;
    const __half* Bh = z ? Bh1 : Bh0;
    const float* bias = z ? b1 : b0;
    int m0 = blockIdx.y * 128, n0 = blockIdx.x * 128;
    if (t < 128) s_bias[t] = bias[n0 + t];

    float acc[4][4][4];
    #pragma unroll
    for (int mi = 0; mi < 4; mi++)
        #pragma unroll
        for (int ni = 0; ni < 4; ni++)
            #pragma unroll
            for (int r = 0; r < 4; r++) acc[mi][ni][r] = 0.f;

    gemm_body(Ah, Al, Bh, QHD, m0, n0, base, t, acc);

    const int lid = t & 31;
    const int mb = m0 + ((t >> 5) & 1) * 64;
    const int nb = n0 + (t >> 6) * 32;
    const int boff = z ? (NBQ * VQn) : 0;
    #pragma unroll
    for (int mi = 0; mi < 4; mi++) {
        int r0 = mb + mi*16 + (lid >> 2);
        #pragma unroll
        for (int ni = 0; ni < 4; ni++) {
            int n = nb + ni*8 + (lid & 3)*2;
            float v00 = acc[mi][ni][0] + s_bias[n   - n0];
            float v01 = acc[mi][ni][1] + s_bias[n+1 - n0];
            float v10 = acc[mi][ni][2] + s_bias[n   - n0];
            float v11 = acc[mi][ni][3] + s_bias[n+1 - n0];
            int vq = n / QHD, h = n - vq * QHD;
            int b0i = r0 >> 6, q0 = r0 & 63;
            int r1 = r0 + 8;
            int b1i = r1 >> 6, q1 = r1 & 63;
            size_t o0 = ((size_t)(b0i*OUTROWS + boff + q0*VQn + vq)) * QHD + h;
            size_t o1 = ((size_t)(b1i*OUTROWS + boff + q1*VQn + vq)) * QHD + h;
            outf[o0]   = v00; outf[o0+1] = v01;
            outf[o1]   = v10; outf[o1+1] = v11;
        }
    }
}

__global__ void write_mask(const float* __restrict__ box_qmask,
                           const float* __restrict__ click_qmask,
                           float* __restrict__ out_mask) {
    int i = blockIdx.x * blockDim.x + threadIdx.x;
    if (i >= NB * OUTROWS) return;
    int b = i >> 10, r = i & 1023;
    float v = (r < NBQ*VQn) ? box_qmask[b*NBQ + (r >> 3)]
                            : click_qmask[b*NCK + ((r - NBQ*VQn) >> 3)];
    out_mask[i] = v;
}

// ================= host =================
extern "C" void kernel_launch(void* const* d_in, const int* in_sizes, int n_in,
                              void* d_out, int out_size) {
    const float* sem     = (const float*)d_in[0];
    const float* propf   = (const float*)d_in[1];
    const float* boxc    = (const float*)d_in[2];
    const float* encxyz  = (const float*)d_in[3];
    const float* encf    = (const float*)d_in[4];
    const float* pcmin   = (const float*)d_in[5];
    const float* pcmax   = (const float*)d_in[6];
    const float* boxq    = (const float*)d_in[7];
    const float* boxqm   = (const float*)d_in[8];
    const float* clickq  = (const float*)d_in[9];
    const float* clickqm = (const float*)d_in[10];
    const float* gauss   = (const float*)d_in[11];
    const float* bw1     = (const float*)d_in[12];
    const float* bb1     = (const float*)d_in[13];
    const float* bw2     = (const float*)d_in[14];
    const float* bb2     = (const float*)d_in[15];
    const float* cw1     = (const float*)d_in[16];
    const float* cb1     = (const float*)d_in[17];
    const float* cw2     = (const float*)d_in[18];
    const float* cb2     = (const float*)d_in[19];
    float* out = (float*)d_out;

    void *bxh, *bxl, *ckh, *ckl, *w1bh, *w1ch, *w2bh, *w2ch, *h1h, *h1l, *h2h, *h2l;
    cudaGetSymbolAddress(&bxh,  g_bxA_h); cudaGetSymbolAddress(&bxl,  g_bxA_l);
    cudaGetSymbolAddress(&ckh,  g_ckA_h); cudaGetSymbolAddress(&ckl,  g_ckA_l);
    cudaGetSymbolAddress(&w1bh, g_w1b_h); cudaGetSymbolAddress(&w1ch, g_w1c_h);
    cudaGetSymbolAddress(&w2bh, g_w2b_h); cudaGetSymbolAddress(&w2ch, g_w2c_h);
    cudaGetSymbolAddress(&h1h,  g_h1_h);  cudaGetSymbolAddress(&h1l,  g_h1_l);
    cudaGetSymbolAddress(&h2h,  g_h2_h);  cudaGetSymbolAddress(&h2l,  g_h2_l);

    cudaFuncSetAttribute(tgemm_l1, cudaFuncAttributeMaxDynamicSharedMemorySize, SMEM_NEED);
    cudaFuncSetAttribute(tgemm_l2, cudaFuncAttributeMaxDynamicSharedMemorySize, SMEM_NEED);

    prop_prep<<<(NB*NPROP + 127)/128, 128>>>(sem, boxc);
    nn_init<<<(MROWS + 255)/256, 256>>>();
    box_match<<<NB, 256>>>(boxq);
    gather_box<<<MROWS, 64>>>(propf);
    click_nn<<<dim3(NB, NPTS/NN_PTS), 256>>>(encxyz, clickq);
    click_build<<<MROWS, 128>>>(encf, clickq, pcmin, pcmax, gauss);

    {
        dim3 blk(32, 8);
        tconv<<<dim3(QHD/32, CDIM/32),    blk>>>(bw1, (__half*)w1bh, CDIM,   QHD);
        tconv<<<dim3(QHD/32, 2*CDIM/32),  blk>>>(cw1, (__half*)w1ch, 2*CDIM, QHD);
        tconv<<<dim3(VQn*QHD/32, QHD/32), blk>>>(bw2, (__half*)w2bh, QHD, VQn*QHD);
        tconv<<<dim3(VQn*QHD/32, QHD/32), blk>>>(cw2, (__half*)w2ch, QHD, VQn*QHD);
    }

    // layer 1: both branches in one launch (z=2), M=2048, N=768
    tgemm_l1<<<dim3(QHD/128, MROWS/128, 2), 256, SMEM_NEED>>>(
        (__half*)bxh, (__half*)bxl, (__half*)w1bh, bb1, CDIM,   (__half*)h1h, (__half*)h1l,
        (__half*)ckh, (__half*)ckl, (__half*)w1ch, cb1, 2*CDIM, (__half*)h2h, (__half*)h2l);

    // layer 2: both branches in one launch (z=2), M=2048, N=6144
    tgemm_l2<<<dim3(VQn*QHD/128, MROWS/128, 2), 256, SMEM_NEED>>>(
        (__half*)h1h, (__half*)h1l, (__half*)w2bh, bb2,
        (__half*)h2h, (__half*)h2l, (__half*)w2ch, cb2, out);

    write_mask<<<(NB*OUTROWS + 255)/256, 256>>>(boxqm, clickqm, out + FEAT_ELEMS);
}

// round 7
// speedup vs baseline: 4.6062x; 1.6371x over previous
#include <cuda_runtime.h>
#include <cuda_fp16.h>
#include <math_constants.h>
#include <cstdint>

#define NB 32
#define NPROP 256
#define NCLS 19
#define NPTS 4096
#define NBQ 64
#define NCK 64
#define CDIM 256
#define QHD 768
#define VQn 8
#define MROWS (NB*NBQ)                 // 2048
#define OUTROWS 1024
#define FEAT_ELEMS (NB*OUTROWS*QHD)    // 25165824

// ================= device scratch =================
__device__ float g_mn[NB*NPROP*3];
__device__ float g_mx[NB*NPROP*3];
__device__ float g_vol[NB*NPROP];
__device__ float g_pmask[NB*NPROP];
__device__ int   g_match[MROWS];
__device__ unsigned long long g_nnpack[MROWS];

// fp16 operands: layer-1 A split hi/lo (exact), weights fp16, hidden fp16
__device__ __half g_bxA_h[MROWS*CDIM],   g_bxA_l[MROWS*CDIM];     // [2048,256]
__device__ __half g_ckA_h[MROWS*2*CDIM], g_ckA_l[MROWS*2*CDIM];   // [2048,512]
__device__ __half g_w1b_h[QHD*CDIM];                              // [768,256]  (N,K)
__device__ __half g_w1c_h[QHD*2*CDIM];                            // [768,512]
__device__ __half g_w2b_h[VQn*QHD*QHD];                           // [6144,768]
__device__ __half g_w2c_h[VQn*QHD*QHD];                           // [6144,768]
__device__ __half g_h1[MROWS*QHD];                                // box hidden fp16
__device__ __half g_h2[MROWS*QHD];                                // click hidden fp16

// ================= helpers =================
__device__ __forceinline__ uint32_t smem_u32(const void* p) {
    uint32_t a;
    asm("{ .reg .u64 t; cvta.to.shared.u64 t, %1; cvt.u32.u64 %0, t; }" : "=r"(a) : "l"(p));
    return a;
}
__device__ __forceinline__ void cp16(uint32_t dst, const void* src) {
    asm volatile("cp.async.cg.shared.global [%0], [%1], 16;" :: "r"(dst), "l"(src));
}
#define CP_COMMIT() asm volatile("cp.async.commit_group;" ::: "memory")
#define CP_WAIT1()  asm volatile("cp.async.wait_group 1;" ::: "memory")

__device__ __forceinline__ void ldsm_x4(uint32_t* r, uint32_t addr) {
    asm volatile("ldmatrix.sync.aligned.m8n8.x4.shared.b16 {%0,%1,%2,%3}, [%4];"
        : "=r"(r[0]), "=r"(r[1]), "=r"(r[2]), "=r"(r[3]) : "r"(addr));
}
__device__ __forceinline__ void ldsm_x2(uint32_t* r, uint32_t addr) {
    asm volatile("ldmatrix.sync.aligned.m8n8.x2.shared.b16 {%0,%1}, [%2];"
        : "=r"(r[0]), "=r"(r[1]) : "r"(addr));
}
__device__ __forceinline__ void mma16816(float* d, const uint32_t* a, const uint32_t* b) {
    asm volatile(
        "mma.sync.aligned.m16n8k16.row.col.f32.f16.f16.f32 "
        "{%0,%1,%2,%3}, {%4,%5,%6,%7}, {%8,%9}, {%0,%1,%2,%3};"
        : "+f"(d[0]), "+f"(d[1]), "+f"(d[2]), "+f"(d[3])
        : "r"(a[0]), "r"(a[1]), "r"(a[2]), "r"(a[3]), "r"(b[0]), "r"(b[1]));
}
__device__ __forceinline__ void hsplit(float x, __half* h, __half* l) {
    __half hi = __float2half_rn(x);
    *h = hi;
    *l = __float2half_rn(x - __half2float(hi));
}

// ================= prep kernels =================
__global__ void prop_prep(const float* __restrict__ logits, const float* __restrict__ corners) {
    int p = blockIdx.x * blockDim.x + threadIdx.x;
    if (p >= NB*NPROP) return;
    const float* l = logits + (size_t)p * NCLS;
    float best = l[0]; int bi = 0;
    #pragma unroll
    for (int k = 1; k < NCLS; k++) { float v = l[k]; if (v > best) { best = v; bi = k; } }
    g_pmask[p] = (bi != NCLS - 1) ? 1.f : 0.f;
    const float* cr = corners + (size_t)p * 24;
    float mn0 = cr[0], mn1 = cr[1], mn2 = cr[2];
    float mx0 = cr[0], mx1 = cr[1], mx2 = cr[2];
    #pragma unroll
    for (int c = 1; c < 8; c++) {
        float x = cr[c*3+0], y = cr[c*3+1], z = cr[c*3+2];
        mn0 = fminf(mn0, x); mx0 = fmaxf(mx0, x);
        mn1 = fminf(mn1, y); mx1 = fmaxf(mx1, y);
        mn2 = fminf(mn2, z); mx2 = fmaxf(mx2, z);
    }
    g_mn[p*3+0] = mn0; g_mn[p*3+1] = mn1; g_mn[p*3+2] = mn2;
    g_mx[p*3+0] = mx0; g_mx[p*3+1] = mx1; g_mx[p*3+2] = mx2;
    g_vol[p] = (mx0-mn0)*(mx1-mn1)*(mx2-mn2);
}

__global__ void nn_init() {
    int i = blockIdx.x * blockDim.x + threadIdx.x;
    if (i < MROWS) g_nnpack[i] = ~0ull;
}

__global__ void box_match(const float* __restrict__ box_query) {
    __shared__ float s_mn[NPROP*3], s_mx[NPROP*3], s_vol[NPROP], s_msk[NPROP];
    int b = blockIdx.x, t = threadIdx.x;
    if (t < NPROP) {
        int p = b*NPROP + t;
        s_mn[t*3+0] = g_mn[p*3+0]; s_mn[t*3+1] = g_mn[p*3+1]; s_mn[t*3+2] = g_mn[p*3+2];
        s_mx[t*3+0] = g_mx[p*3+0]; s_mx[t*3+1] = g_mx[p*3+1]; s_mx[t*3+2] = g_mx[p*3+2];
        s_vol[t] = g_vol[p]; s_msk[t] = g_pmask[p];
    }
    __syncthreads();
    if (t < NBQ) {
        const float* cq = box_query + ((size_t)b*NBQ + t) * 24;
        float mn0 = cq[0], mn1 = cq[1], mn2 = cq[2];
        float mx0 = cq[0], mx1 = cq[1], mx2 = cq[2];
        #pragma unroll
        for (int c = 1; c < 8; c++) {
            float x = cq[c*3+0], y = cq[c*3+1], z = cq[c*3+2];
            mn0 = fminf(mn0, x); mx0 = fmaxf(mx0, x);
            mn1 = fminf(mn1, y); mx1 = fmaxf(mx1, y);
            mn2 = fminf(mn2, z); mx2 = fmaxf(mx2, z);
        }
        float volq = (mx0-mn0)*(mx1-mn1)*(mx2-mn2);
        float best = -1.f; int bi = 0;
        for (int p = 0; p < NPROP; p++) {
            float ix = fmaxf(fminf(mx0, s_mx[p*3+0]) - fmaxf(mn0, s_mn[p*3+0]), 0.f);
            float iy = fmaxf(fminf(mx1, s_mx[p*3+1]) - fmaxf(mn1, s_mn[p*3+1]), 0.f);
            float iz = fmaxf(fminf(mx2, s_mx[p*3+2]) - fmaxf(mn2, s_mn[p*3+2]), 0.f);
            float inter = ix*iy*iz;
            float iou = inter / (volq + s_vol[p] - inter + 1e-8f) * s_msk[p];
            if (iou > best) { best = iou; bi = p; }
        }
        g_match[b*NBQ + t] = bi;
    }
}

__global__ void gather_box(const float* __restrict__ prop_features) {
    int r = blockIdx.x;
    int b = r >> 6;
    int m = g_match[r];
    const float4* src = (const float4*)(prop_features + ((size_t)b*NPROP + m) * CDIM);
    float4 v = src[threadIdx.x];
    int o = r*CDIM + threadIdx.x*4;
    hsplit(v.x, &g_bxA_h[o+0], &g_bxA_l[o+0]);
    hsplit(v.y, &g_bxA_h[o+1], &g_bxA_l[o+1]);
    hsplit(v.z, &g_bxA_h[o+2], &g_bxA_l[o+2]);
    hsplit(v.w, &g_bxA_h[o+3], &g_bxA_l[o+3]);
}

#define NN_PTS 512
__global__ void click_nn(const float* __restrict__ enc_xyz, const float* __restrict__ click_query) {
    __shared__ float s_xyz[NN_PTS*3];
    int b = blockIdx.x, ck = blockIdx.y, t = threadIdx.x;
    const float* src = enc_xyz + ((size_t)b*NPTS + ck*NN_PTS) * 3;
    for (int i = t; i < NN_PTS*3; i += 256) s_xyz[i] = src[i];
    __syncthreads();
    int warp = t >> 5, lane = t & 31;
    for (int q = warp; q < NCK; q += 8) {
        const float* cq = click_query + ((size_t)b*NCK + q) * 3;
        float cx = cq[0], cy = cq[1], cz = cq[2];
        float best = CUDART_INF_F; int bi = 0;
        for (int p = lane; p < NN_PTS; p += 32) {
            float dx = cx - s_xyz[p*3+0];
            float dy = cy - s_xyz[p*3+1];
            float dz = cz - s_xyz[p*3+2];
            float d = dx*dx + dy*dy + dz*dz;
            if (d < best) { best = d; bi = p; }
        }
        #pragma unroll
        for (int off = 16; off; off >>= 1) {
            float ob = __shfl_xor_sync(0xffffffffu, best, off);
            int   oi = __shfl_xor_sync(0xffffffffu, bi, off);
            if (ob < best || (ob == best && oi < bi)) { best = ob; bi = oi; }
        }
        if (lane == 0) {
            unsigned long long key = ((unsigned long long)__float_as_uint(best) << 32)
                                   | (unsigned)(ck*NN_PTS + bi);
            atomicMin(&g_nnpack[b*NCK + q], key);
        }
    }
}

__global__ void click_build(const float* __restrict__ enc_features,
                            const float* __restrict__ click_query,
                            const float* __restrict__ pc_min,
                            const float* __restrict__ pc_max,
                            const float* __restrict__ gauss) {
    int r = blockIdx.x, t = threadIdx.x;  // 128 threads
    int b = r >> 6;
    int nn = (int)(g_nnpack[r] & 0xffffffffull);
    const float2* src = (const float2*)(enc_features + ((size_t)b*NPTS + nn) * CDIM);
    float2 v = src[t];
    int o = r*2*CDIM + 2*t;
    hsplit(v.x, &g_ckA_h[o+0], &g_ckA_l[o+0]);
    hsplit(v.y, &g_ckA_h[o+1], &g_ckA_l[o+1]);
    const float* cq = click_query + (size_t)r * 3;
    float pr = 0.f;
    #pragma unroll
    for (int d = 0; d < 3; d++) {
        float x01 = (cq[d] - pc_min[b*3+d]) / (pc_max[b*3+d] - pc_min[b*3+d]);
        pr += x01 * 6.283185307179586f * gauss[d*(CDIM/2) + t];
    }
    int ps  = r*2*CDIM + CDIM + t;
    int pcs = r*2*CDIM + CDIM + 128 + t;
    hsplit(sinf(pr), &g_ckA_h[ps],  &g_ckA_l[ps]);
    hsplit(cosf(pr), &g_ckA_h[pcs], &g_ckA_l[pcs]);
}

// transpose + fp16 convert: src [K,N] f32 -> dst [N,K] fp16
__global__ void tconv(const float* __restrict__ src, __half* __restrict__ dh, int K, int N) {
    __shared__ float tile[32][33];
    int n0 = blockIdx.x*32, k0 = blockIdx.y*32;
    int tx = threadIdx.x, ty = threadIdx.y;
    #pragma unroll
    for (int j = 0; j < 4; j++)
        tile[ty + 8*j][tx] = src[(size_t)(k0 + ty + 8*j) * N + n0 + tx];
    __syncthreads();
    #pragma unroll
    for (int j = 0; j < 4; j++)
        dh[(size_t)(n0 + ty + 8*j) * K + k0 + tx] = __float2half_rn(tile[tx][ty + 8*j]);
}

// ================= HMMA GEMM =================
// 128x128 CTA tile, BK=32, 8 warps (2M x 4N), warp tile 64x32.
// 3-stage cp.async ring, ONE __syncthreads per slab.
// SPLIT_A: D = Ah*Bh + Al*Bh (layer 1, exact A); else D = A*B (layer 2).
#define ROWB 80
#define TILE_B (128*ROWB)            // 10240
#define NSTAGE 3

template <bool SPLIT_A>
__device__ __forceinline__ void gemm_body(
        const __half* __restrict__ Ah, const __half* __restrict__ Al,
        const __half* __restrict__ Bh,
        int K, int m0, int n0, uint32_t base, int t, float acc[4][4][4]) {
    constexpr int NT = SPLIT_A ? 3 : 2;
    constexpr int STAGE_B = NT * TILE_B;
    const int lid = t & 31;
    const int mwarp = (t >> 5) & 1, nwarp = t >> 6;
    const int S = K >> 5;

    auto load_slab = [&](int s) {
        uint32_t sb = base + (s % NSTAGE) * STAGE_B;
        size_t kof = (size_t)s * 32;
        #pragma unroll
        for (int i = 0; i < 2*NT; i++) {
            int c = i * 256 + t;
            int tile = c >> 9, local = c & 511;
            int row = local >> 2, chk = local & 3;
            uint32_t dst = sb + tile * TILE_B + row * ROWB + chk * 16;
            const __half* srcp;
            if (SPLIT_A) {
                if      (tile == 0) srcp = Ah + (size_t)(m0 + row) * K + kof + chk * 8;
                else if (tile == 1) srcp = Al + (size_t)(m0 + row) * K + kof + chk * 8;
                else                srcp = Bh + (size_t)(n0 + row) * K + kof + chk * 8;
            } else {
                if (tile == 0) srcp = Ah + (size_t)(m0 + row) * K + kof + chk * 8;
                else           srcp = Bh + (size_t)(n0 + row) * K + kof + chk * 8;
            }
            cp16(dst, srcp);
        }
    };

    auto compute_stage = [&](int s) {
        uint32_t sb = base + (s % NSTAGE) * STAGE_B;
        uint32_t aH = sb, aL = sb + TILE_B, bH = sb + (NT - 1) * TILE_B;
        #pragma unroll
        for (int ks = 0; ks < 32; ks += 16) {
            uint32_t ah[4][4], al[4][4], bh[4][2];
            uint32_t aoff = (uint32_t)((mwarp*64 + (lid & 15)) * ROWB
                                       + (ks + ((lid >> 4) << 3)) * 2);
            #pragma unroll
            for (int mi = 0; mi < 4; mi++) {
                ldsm_x4(ah[mi], aH + aoff + mi*16*ROWB);
                if (SPLIT_A) ldsm_x4(al[mi], aL + aoff + mi*16*ROWB);
            }
            uint32_t boff = (uint32_t)((nwarp*32 + (lid & 7)) * ROWB
                                       + (ks + (((lid >> 3) & 1) << 3)) * 2);
            #pragma unroll
            for (int ni = 0; ni < 4; ni++)
                ldsm_x2(bh[ni], bH + boff + ni*8*ROWB);
            #pragma unroll
            for (int mi = 0; mi < 4; mi++)
                #pragma unroll
                for (int ni = 0; ni < 4; ni++) {
                    mma16816(acc[mi][ni], ah[mi], bh[ni]);
                    if (SPLIT_A) mma16816(acc[mi][ni], al[mi], bh[ni]);
                }
        }
    };

    load_slab(0); CP_COMMIT();
    if (S > 1) load_slab(1);
    CP_COMMIT();
    for (int s = 0; s < S; s++) {
        CP_WAIT1();            // ensure group s complete (<=1 pending: s+1)
        __syncthreads();       // publish stage s to all warps; stage (s-1)%3 free
        if (s + 2 < S) load_slab(s + 2);
        CP_COMMIT();           // keep group count uniform (may be empty)
        compute_stage(s);
    }
}

// layer 1 (both branches via blockIdx.z): relu(D+bias) -> fp16 hidden
__global__ __launch_bounds__(256, 1) void tgemm_l1(
        const __half* Ah0, const __half* Al0, const __half* Bh0, const float* b0, int K0,
        __half* H0,
        const __half* Ah1, const __half* Al1, const __half* Bh1, const float* b1, int K1,
        __half* H1) {
    extern __shared__ __align__(16) char smem_raw[];
    const uint32_t base = smem_u32(smem_raw);
    float* s_bias = (float*)(smem_raw + NSTAGE * 3 * TILE_B);
    int z = blockIdx.z, t = threadIdx.x;
    const __half* Ah = z ? Ah1 : Ah0;
    const __half* Al = z ? Al1 : Al0;
    const __half* Bh = z ? Bh1 : Bh0;
    const float* bias = z ? b1 : b0;
    int K = z ? K1 : K0;
    __half* H = z ? H1 : H0;
    int m0 = blockIdx.y * 128, n0 = blockIdx.x * 128;
    if (t < 128) s_bias[t] = bias[n0 + t];

    float acc[4][4][4];
    #pragma unroll
    for (int mi = 0; mi < 4; mi++)
        #pragma unroll
        for (int ni = 0; ni < 4; ni++)
            #pragma unroll
            for (int r = 0; r < 4; r++) acc[mi][ni][r] = 0.f;

    gemm_body<true>(Ah, Al, Bh, K, m0, n0, base, t, acc);

    const int lid = t & 31;
    const int mb = m0 + ((t >> 5) & 1) * 64;
    const int nb = n0 + (t >> 6) * 32;
    #pragma unroll
    for (int mi = 0; mi < 4; mi++) {
        int r0 = mb + mi*16 + (lid >> 2);
        #pragma unroll
        for (int ni = 0; ni < 4; ni++) {
            int n = nb + ni*8 + (lid & 3)*2;
            float v00 = fmaxf(acc[mi][ni][0] + s_bias[n   - n0], 0.f);
            float v01 = fmaxf(acc[mi][ni][1] + s_bias[n+1 - n0], 0.f);
            float v10 = fmaxf(acc[mi][ni][2] + s_bias[n   - n0], 0.f);
            float v11 = fmaxf(acc[mi][ni][3] + s_bias[n+1 - n0], 0.f);
            size_t o0 = (size_t)r0 * QHD + n;
            size_t o1 = (size_t)(r0 + 8) * QHD + n;
            H[o0]   = __float2half_rn(v00);
            H[o0+1] = __float2half_rn(v01);
            H[o1]   = __float2half_rn(v10);
            H[o1+1] = __float2half_rn(v11);
        }
    }
}

// layer 2 (both branches via blockIdx.z): D+bias -> out remapped (b,q,v,h)
__global__ __launch_bounds__(256, 2) void tgemm_l2(
        const __half* A0, const __half* B0, const float* b0,
        const __half* A1, const __half* B1, const float* b1,
        float* __restrict__ outf) {
    extern __shared__ __align__(16) char smem_raw[];
    const uint32_t base = smem_u32(smem_raw);
    float* s_bias = (float*)(smem_raw + NSTAGE * 2 * TILE_B);
    int z = blockIdx.z, t = threadIdx.x;
    const __half* A = z ? A1 : A0;
    const __half* B = z ? B1 : B0;
    const float* bias = z ? b1 : b0;
    int m0 = blockIdx.y * 128, n0 = blockIdx.x * 128;
    if (t < 128) s_bias[t] = bias[n0 + t];

    float acc[4][4][4];
    #pragma unroll
    for (int mi = 0; mi < 4; mi++)
        #pragma unroll
        for (int ni = 0; ni < 4; ni++)
            #pragma unroll
            for (int r = 0; r < 4; r++) acc[mi][ni][r] = 0.f;

    gemm_body<false>(A, nullptr, B, QHD, m0, n0, base, t, acc);

    const int lid = t & 31;
    const int mb = m0 + ((t >> 5) & 1) * 64;
    const int nb = n0 + (t >> 6) * 32;
    const int boff = z ? (NBQ * VQn) : 0;
    #pragma unroll
    for (int mi = 0; mi < 4; mi++) {
        int r0 = mb + mi*16 + (lid >> 2);
        #pragma unroll
        for (int ni = 0; ni < 4; ni++) {
            int n = nb + ni*8 + (lid & 3)*2;
            float v00 = acc[mi][ni][0] + s_bias[n   - n0];
            float v01 = acc[mi][ni][1] + s_bias[n+1 - n0];
            float v10 = acc[mi][ni][2] + s_bias[n   - n0];
            float v11 = acc[mi][ni][3] + s_bias[n+1 - n0];
            int vq = n / QHD, h = n - vq * QHD;
            int b0i = r0 >> 6, q0 = r0 & 63;
            int r1 = r0 + 8;
            int b1i = r1 >> 6, q1 = r1 & 63;
            size_t o0 = ((size_t)(b0i*OUTROWS + boff + q0*VQn + vq)) * QHD + h;
            size_t o1 = ((size_t)(b1i*OUTROWS + boff + q1*VQn + vq)) * QHD + h;
            outf[o0]   = v00; outf[o0+1] = v01;
            outf[o1]   = v10; outf[o1+1] = v11;
        }
    }
}

__global__ void write_mask(const float* __restrict__ box_qmask,
                           const float* __restrict__ click_qmask,
                           float* __restrict__ out_mask) {
    int i = blockIdx.x * blockDim.x + threadIdx.x;
    if (i >= NB * OUTROWS) return;
    int b = i >> 10, r = i & 1023;
    float v = (r < NBQ*VQn) ? box_qmask[b*NBQ + (r >> 3)]
                            : click_qmask[b*NCK + ((r - NBQ*VQn) >> 3)];
    out_mask[i] = v;
}

// ================= host =================
extern "C" void kernel_launch(void* const* d_in, const int* in_sizes, int n_in,
                              void* d_out, int out_size) {
    const float* sem     = (const float*)d_in[0];
    const float* propf   = (const float*)d_in[1];
    const float* boxc    = (const float*)d_in[2];
    const float* encxyz  = (const float*)d_in[3];
    const float* encf    = (const float*)d_in[4];
    const float* pcmin   = (const float*)d_in[5];
    const float* pcmax   = (const float*)d_in[6];
    const float* boxq    = (const float*)d_in[7];
    const float* boxqm   = (const float*)d_in[8];
    const float* clickq  = (const float*)d_in[9];
    const float* clickqm = (const float*)d_in[10];
    const float* gauss   = (const float*)d_in[11];
    const float* bw1     = (const float*)d_in[12];
    const float* bb1     = (const float*)d_in[13];
    const float* bw2     = (const float*)d_in[14];
    const float* bb2     = (const float*)d_in[15];
    const float* cw1     = (const float*)d_in[16];
    const float* cb1     = (const float*)d_in[17];
    const float* cw2     = (const float*)d_in[18];
    const float* cb2     = (const float*)d_in[19];
    float* out = (float*)d_out;

    void *bxh, *bxl, *ckh, *ckl, *w1bh, *w1ch, *w2bh, *w2ch, *h1, *h2;
    cudaGetSymbolAddress(&bxh,  g_bxA_h); cudaGetSymbolAddress(&bxl,  g_bxA_l);
    cudaGetSymbolAddress(&ckh,  g_ckA_h); cudaGetSymbolAddress(&ckl,  g_ckA_l);
    cudaGetSymbolAddress(&w1bh, g_w1b_h); cudaGetSymbolAddress(&w1ch, g_w1c_h);
    cudaGetSymbolAddress(&w2bh, g_w2b_h); cudaGetSymbolAddress(&w2ch, g_w2c_h);
    cudaGetSymbolAddress(&h1,   g_h1);    cudaGetSymbolAddress(&h2,   g_h2);

    const int smem_l1 = NSTAGE * 3 * TILE_B + 512;   // 92672
    const int smem_l2 = NSTAGE * 2 * TILE_B + 512;   // 61952
    cudaFuncSetAttribute(tgemm_l1, cudaFuncAttributeMaxDynamicSharedMemorySize, smem_l1);
    cudaFuncSetAttribute(tgemm_l2, cudaFuncAttributeMaxDynamicSharedMemorySize, smem_l2);

    prop_prep<<<(NB*NPROP + 127)/128, 128>>>(sem, boxc);
    nn_init<<<(MROWS + 255)/256, 256>>>();
    box_match<<<NB, 256>>>(boxq);
    gather_box<<<MROWS, 64>>>(propf);
    click_nn<<<dim3(NB, NPTS/NN_PTS), 256>>>(encxyz, clickq);
    click_build<<<MROWS, 128>>>(encf, clickq, pcmin, pcmax, gauss);

    {
        dim3 blk(32, 8);
        tconv<<<dim3(QHD/32, CDIM/32),    blk>>>(bw1, (__half*)w1bh, CDIM,   QHD);
        tconv<<<dim3(QHD/32, 2*CDIM/32),  blk>>>(cw1, (__half*)w1ch, 2*CDIM, QHD);
        tconv<<<dim3(VQn*QHD/32, QHD/32), blk>>>(bw2, (__half*)w2bh, QHD, VQn*QHD);
        tconv<<<dim3(VQn*QHD/32, QHD/32), blk>>>(cw2, (__half*)w2ch, QHD, VQn*QHD);
    }

    // layer 1: both branches in one launch (z=2), M=2048, N=768
    tgemm_l1<<<dim3(QHD/128, MROWS/128, 2), 256, smem_l1>>>(
        (__half*)bxh, (__half*)bxl, (__half*)w1bh, bb1, CDIM,   (__half*)h1,
        (__half*)ckh, (__half*)ckl, (__half*)w1ch, cb1, 2*CDIM, (__half*)h2);

    // layer 2: both branches in one launch (z=2), M=2048, N=6144
    tgemm_l2<<<dim3(VQn*QHD/128, MROWS/128, 2), 256, smem_l2>>>(
        (__half*)h1, (__half*)w2bh, bb2,
        (__half*)h2, (__half*)w2ch, cb2, out);

    write_mask<<<(NB*OUTROWS + 255)/256, 256>>>(boxqm, clickqm, out + FEAT_ELEMS);
}